// round 2
// baseline (speedup 1.0000x reference)
#include <cuda_runtime.h>
#include <math.h>

// Problem constants (from reference setup_inputs)
#define B_ 2
#define S_ 2048
#define D_ 1024
#define H_ 16
#define DK_ 64

// Scratch (allocation-free rule: __device__ globals)
__device__ float g_q[B_ * S_ * D_];     // [B,H,S,64]
__device__ float g_k[B_ * S_ * D_];     // [B,H,S,64]
__device__ float g_v[B_ * S_ * D_];     // [B,H,S,64]
__device__ float g_attn[B_ * S_ * D_];  // [B,S,H,64] == [M, D]
__device__ float2 g_sc[S_ * 32];        // per (s, pair): (sin, cos)

// ---------------------------------------------------------------------------
// sin/cos table: matches reference fp32 ang = pos * inv_freq, then accurate
// range reduction in double so sincosf is precise even under fast-math.
// ---------------------------------------------------------------------------
__global__ void sincos_table_kernel(const int* __restrict__ pos) {
    int idx = blockIdx.x * blockDim.x + threadIdx.x;
    if (idx >= S_ * 32) return;
    int s = idx >> 5;
    int p = idx & 31;
    // inv_freq = 10000^(-p/32), computed in double then rounded to fp32
    float invf = (float)exp2(-(double)p * 0.4152410118609203);  // log2(1e4)/32
    float ang  = (float)pos[s] * invf;                          // fp32, like ref
    double a   = (double)ang;
    double kq  = floor(a * 0.15915494309189535);                // 1/(2pi)
    float r    = (float)(a - kq * 6.283185307179586);
    float sn, cs;
    sincosf(r, &sn, &cs);
    g_sc[idx] = make_float2(sn, cs);
}

// ---------------------------------------------------------------------------
// RoPE apply, in place on [B,H,S,64] tensor. One thread per (even,odd) pair.
// ---------------------------------------------------------------------------
__global__ void rope_kernel(float* __restrict__ X) {
    int idx = blockIdx.x * blockDim.x + threadIdx.x;  // over B*H*S*32 pairs
    int p = idx & 31;
    int rowId = idx >> 5;         // (b*H + h)*S + s
    int s = rowId & (S_ - 1);
    float2 sc = g_sc[(s << 5) | p];
    float2 v = ((float2*)X)[idx];
    ((float2*)X)[idx] = make_float2(v.x * sc.y - v.y * sc.x,
                                    v.x * sc.x + v.y * sc.y);
}

// ---------------------------------------------------------------------------
// SGEMM: C[M,N] = A[M,K] @ W[N,K]^T   (y = x @ W^T, the einsum 'bsd,ed->bse')
// 128x128 tile, K-tile 8, 256 threads, 8x8 per-thread microtile.
// HEADED: write C to [B, H, S, 64] layout (head split) instead of row-major.
// ---------------------------------------------------------------------------
template <bool HEADED>
__global__ void __launch_bounds__(256) sgemm_tn(const float* __restrict__ A,
                                                const float* __restrict__ W,
                                                float* __restrict__ C) {
    __shared__ float As[8][128];
    __shared__ float Bs[8][128];
    const int K = D_;

    int tid = threadIdx.x;
    int tx = tid & 15;
    int ty = tid >> 4;
    int rowBase = blockIdx.y * 128;
    int colBase = blockIdx.x * 128;

    int lr = tid >> 1;         // 0..127
    int lk = (tid & 1) * 4;    // 0 or 4

    const float* Ap = A + (size_t)(rowBase + lr) * K + lk;
    const float* Wp = W + (size_t)(colBase + lr) * K + lk;

    float acc[8][8];
#pragma unroll
    for (int i = 0; i < 8; i++)
#pragma unroll
        for (int j = 0; j < 8; j++) acc[i][j] = 0.0f;

    for (int kt = 0; kt < K; kt += 8) {
        float4 av = *(const float4*)(Ap + kt);
        float4 wv = *(const float4*)(Wp + kt);
        As[lk + 0][lr] = av.x;
        As[lk + 1][lr] = av.y;
        As[lk + 2][lr] = av.z;
        As[lk + 3][lr] = av.w;
        Bs[lk + 0][lr] = wv.x;
        Bs[lk + 1][lr] = wv.y;
        Bs[lk + 2][lr] = wv.z;
        Bs[lk + 3][lr] = wv.w;
        __syncthreads();

#pragma unroll
        for (int k = 0; k < 8; k++) {
            float ar[8], br[8];
            *(float4*)&ar[0] = *(const float4*)&As[k][ty * 8];
            *(float4*)&ar[4] = *(const float4*)&As[k][ty * 8 + 4];
            *(float4*)&br[0] = *(const float4*)&Bs[k][tx * 8];
            *(float4*)&br[4] = *(const float4*)&Bs[k][tx * 8 + 4];
#pragma unroll
            for (int i = 0; i < 8; i++)
#pragma unroll
                for (int j = 0; j < 8; j++) acc[i][j] += ar[i] * br[j];
        }
        __syncthreads();
    }

#pragma unroll
    for (int i = 0; i < 8; i++) {
        int m = rowBase + ty * 8 + i;
#pragma unroll
        for (int j = 0; j < 8; j += 4) {
            int n = colBase + tx * 8 + j;
            float4 val = make_float4(acc[i][j], acc[i][j + 1], acc[i][j + 2],
                                     acc[i][j + 3]);
            if (HEADED) {
                int b = m >> 11;        // S_ = 2048
                int s = m & (S_ - 1);
                int h = n >> 6;         // DK_ = 64
                int d = n & 63;
                *(float4*)&C[((((size_t)b * H_ + h) * S_ + s) << 6) + d] = val;
            } else {
                *(float4*)&C[(size_t)m * D_ + n] = val;
            }
        }
    }
}

// ---------------------------------------------------------------------------
// Causal flash attention, fp32. Q,K,V: [B,H,S,64]. O: [B,S,H,64].
// One thread owns one q row -> softmax state is thread-local (no reductions).
// BM = 128 q rows/CTA (128 threads), BN = 64 k rows per smem tile.
// ---------------------------------------------------------------------------
__global__ void __launch_bounds__(128) attn_kernel(const float* __restrict__ Q,
                                                   const float* __restrict__ K,
                                                   const float* __restrict__ V,
                                                   float* __restrict__ O) {
    __shared__ float Ks[64 * DK_];
    __shared__ float Vs[64 * DK_];

    int bh = blockIdx.y;        // b*H + h
    int b = bh >> 4;            // H_ = 16
    int h = bh & 15;
    int row = blockIdx.x * 128 + threadIdx.x;

    const float* qp = Q + ((size_t)bh * S_ + row) * DK_;
    float q[DK_];
#pragma unroll
    for (int i = 0; i < 16; i++) ((float4*)q)[i] = ((const float4*)qp)[i];

    float o[DK_];
#pragma unroll
    for (int i = 0; i < DK_; i++) o[i] = 0.0f;

    float m2 = -INFINITY;  // running max in log2 domain
    float l = 0.0f;
    const float sc = 0.125f * 1.4426950408889634f;  // 1/sqrt(64) * log2(e)

    int kend = (blockIdx.x + 1) * 128;  // exclusive (causal: no tiles past diag)
    for (int kb = 0; kb < kend; kb += 64) {
        const float4* kp = (const float4*)(K + ((size_t)bh * S_ + kb) * DK_);
        const float4* vp = (const float4*)(V + ((size_t)bh * S_ + kb) * DK_);
#pragma unroll
        for (int i = 0; i < 8; i++) {
            int f = threadIdx.x + i * 128;  // 0..1023 float4 slots
            ((float4*)Ks)[f] = kp[f];
            ((float4*)Vs)[f] = vp[f];
        }
        __syncthreads();

        int jlim = row - kb + 1;
        if (jlim > 64) jlim = 64;
        for (int j = 0; j < jlim; j++) {
            const float4* kr = (const float4*)&Ks[j * DK_];
            float s = 0.0f;
#pragma unroll
            for (int d4 = 0; d4 < 16; d4++) {
                float4 kk = kr[d4];
                s += q[4 * d4 + 0] * kk.x + q[4 * d4 + 1] * kk.y +
                     q[4 * d4 + 2] * kk.z + q[4 * d4 + 3] * kk.w;
            }
            float t = s * sc;
            const float4* vr = (const float4*)&Vs[j * DK_];
            if (t <= m2) {
                float p = exp2f(t - m2);
                l += p;
#pragma unroll
                for (int d4 = 0; d4 < 16; d4++) {
                    float4 vv = vr[d4];
                    o[4 * d4 + 0] += p * vv.x;
                    o[4 * d4 + 1] += p * vv.y;
                    o[4 * d4 + 2] += p * vv.z;
                    o[4 * d4 + 3] += p * vv.w;
                }
            } else {
                float al = exp2f(m2 - t);
                m2 = t;
                l = l * al + 1.0f;
#pragma unroll
                for (int d4 = 0; d4 < 16; d4++) {
                    float4 vv = vr[d4];
                    o[4 * d4 + 0] = o[4 * d4 + 0] * al + vv.x;
                    o[4 * d4 + 1] = o[4 * d4 + 1] * al + vv.y;
                    o[4 * d4 + 2] = o[4 * d4 + 2] * al + vv.z;
                    o[4 * d4 + 3] = o[4 * d4 + 3] * al + vv.w;
                }
            }
        }
        __syncthreads();
    }

    float inv = 1.0f / l;
    float* op = O + (((size_t)b * S_ + row) * H_ + h) * DK_;
#pragma unroll
    for (int d4 = 0; d4 < 16; d4++) {
        float4 vv = make_float4(o[4 * d4 + 0] * inv, o[4 * d4 + 1] * inv,
                                o[4 * d4 + 2] * inv, o[4 * d4 + 3] * inv);
        ((float4*)op)[d4] = vv;
    }
}

// ---------------------------------------------------------------------------
// Launch: x, Wq, Wk, Wv, Wo, token_positions  ->  out [B,S,D] fp32
// ---------------------------------------------------------------------------
extern "C" void kernel_launch(void* const* d_in, const int* in_sizes, int n_in,
                              void* d_out, int out_size) {
    const float* x  = (const float*)d_in[0];
    const float* Wq = (const float*)d_in[1];
    const float* Wk = (const float*)d_in[2];
    const float* Wv = (const float*)d_in[3];
    const float* Wo = (const float*)d_in[4];
    const int* pos  = (const int*)d_in[5];

    float *q, *k, *v, *attn;
    cudaGetSymbolAddress((void**)&q, g_q);
    cudaGetSymbolAddress((void**)&k, g_k);
    cudaGetSymbolAddress((void**)&v, g_v);
    cudaGetSymbolAddress((void**)&attn, g_attn);

    sincos_table_kernel<<<(S_ * 32) / 256, 256>>>(pos);

    dim3 gg(D_ / 128, (B_ * S_) / 128);  // (8, 32)
    sgemm_tn<true><<<gg, 256>>>(x, Wq, q);
    sgemm_tn<true><<<gg, 256>>>(x, Wk, k);
    sgemm_tn<true><<<gg, 256>>>(x, Wv, v);

    int ropeBlocks = (B_ * H_ * S_ * 32) / 256;
    rope_kernel<<<ropeBlocks, 256>>>(q);
    rope_kernel<<<ropeBlocks, 256>>>(k);

    attn_kernel<<<dim3(S_ / 128, B_ * H_), 128>>>(q, k, v, attn);

    sgemm_tn<false><<<gg, 256>>>(attn, Wo, (float*)d_out);
}

// round 5
// speedup vs baseline: 1.4648x; 1.4648x over previous
#include <cuda_runtime.h>
#include <cuda_bf16.h>
#include <math.h>
#include <cstdint>

// Problem constants
#define B_ 2
#define S_ 2048
#define D_ 1024
#define H_ 16
#define DK_ 64

// ---------------------------------------------------------------------------
// Scratch (__device__ globals; no allocation allowed)
// ---------------------------------------------------------------------------
__device__ float g_q[B_ * S_ * D_];     // [B,H,S,64]
__device__ float g_k[B_ * S_ * D_];     // [B,H,S,64]
__device__ float g_v[B_ * S_ * D_];     // [B,H,S,64]
__device__ float g_attn[B_ * S_ * D_];  // [B,S,H,64] == [M, D]
__device__ float2 g_sc[S_ * 32];

// bf16 split buffers
__device__ __nv_bfloat16 g_xh[B_ * S_ * D_];
__device__ __nv_bfloat16 g_xl[B_ * S_ * D_];
__device__ __nv_bfloat16 g_ah[B_ * S_ * D_];
__device__ __nv_bfloat16 g_al[B_ * S_ * D_];
__device__ __nv_bfloat16 g_wh[4][D_ * D_];
__device__ __nv_bfloat16 g_wl[4][D_ * D_];

// ---------------------------------------------------------------------------
// PTX helpers (baseline ISA only: mma.sync / ldmatrix / cp.async)
// ---------------------------------------------------------------------------
__device__ __forceinline__ uint32_t smem_u32(const void* p) {
    uint32_t a;
    asm("{ .reg .u64 t; cvta.to.shared.u64 t, %1; cvt.u32.u64 %0, t; }"
        : "=r"(a) : "l"(p));
    return a;
}

#define CP16(dst, src) \
    asm volatile("cp.async.cg.shared.global [%0], [%1], 16;" \
                 :: "r"(dst), "l"(src))
#define CP_COMMIT() asm volatile("cp.async.commit_group;")
#define CP_WAIT1() asm volatile("cp.async.wait_group 1;")
#define CP_WAIT0() asm volatile("cp.async.wait_group 0;")

#define LDSM_X4(r, a)                                                       \
    asm volatile("ldmatrix.sync.aligned.m8n8.x4.shared.b16 "                \
                 "{%0,%1,%2,%3}, [%4];"                                     \
                 : "=r"((r)[0]), "=r"((r)[1]), "=r"((r)[2]), "=r"((r)[3])   \
                 : "r"(a))

#define MMA_BF16(d, a, b0, b1)                                              \
    asm volatile("mma.sync.aligned.m16n8k16.row.col.f32.bf16.bf16.f32 "     \
                 "{%0,%1,%2,%3},{%4,%5,%6,%7},{%8,%9},{%0,%1,%2,%3};"       \
                 : "+f"((d)[0]), "+f"((d)[1]), "+f"((d)[2]), "+f"((d)[3])   \
                 : "r"((a)[0]), "r"((a)[1]), "r"((a)[2]), "r"((a)[3]),      \
                   "r"(b0), "r"(b1))

// ---------------------------------------------------------------------------
// fp32 -> (hi, lo) bf16 split
// ---------------------------------------------------------------------------
__global__ void split_kernel(const float* __restrict__ in,
                             __nv_bfloat16* __restrict__ hi,
                             __nv_bfloat16* __restrict__ lo, int n) {
    int i = blockIdx.x * blockDim.x + threadIdx.x;
    if (i >= n) return;
    float v = in[i];
    __nv_bfloat16 h = __float2bfloat16(v);
    hi[i] = h;
    lo[i] = __float2bfloat16(v - __bfloat162float(h));
}

// ---------------------------------------------------------------------------
// HMMA bf16-split GEMM: C[M,1024] = A[M,K=1024] @ W[N,K]^T
// acc = Ah*Wh + Ah*Wl + Al*Wh  (fp32 accum).  Tile 128x128, K-chunk 32,
// 256 thr (8 warps, each 32x64), 2-stage cp.async pipeline.
// smem rows padded to 80B: 8 ldmatrix rows hit banks {0,20,8,28,16,4,24,12}.
// ---------------------------------------------------------------------------
#define NCHUNK 32
#define STRIDE 80
#define TILE_B (128 * STRIDE)   // 10240
#define STAGE_B (4 * TILE_B)    // 40960
#define GSMEM (2 * STAGE_B)     // 81920

template <bool HEADED>
__global__ void __launch_bounds__(256, 1) gemm_mma(
    const __nv_bfloat16* __restrict__ Ah, const __nv_bfloat16* __restrict__ Al,
    const __nv_bfloat16* __restrict__ Bh, const __nv_bfloat16* __restrict__ Bl,
    float* __restrict__ C) {
    extern __shared__ char sm[];
    uint32_t sb = smem_u32(sm);
    int tid = threadIdx.x;
    int lane = tid & 31;
    int wid = tid >> 5;
    int warp_m = wid & 3;   // 4 warps along M (32 rows each)
    int warp_n = wid >> 2;  // 2 warps along N (64 cols each)
    int m0 = blockIdx.y * 128;
    int n0 = blockIdx.x * 128;

    const __nv_bfloat16* gsrc[4] = {
        Ah + (size_t)m0 * D_, Al + (size_t)m0 * D_,
        Bh + (size_t)n0 * D_, Bl + (size_t)n0 * D_};

    int ldrow = tid >> 2;       // 0..63  (x2 -> 128 rows)
    int ldc16 = tid & 3;        // 16B chunk within 64B row

    // ---- stage loader ----
    auto load_stage = [&](int c) {
        uint32_t dbase = sb + (c & 1) * STAGE_B;
#pragma unroll
        for (int op = 0; op < 4; op++) {
#pragma unroll
            for (int i = 0; i < 2; i++) {
                int row = ldrow + i * 64;
                uint32_t dst = dbase + op * TILE_B + row * STRIDE + ldc16 * 16;
                const __nv_bfloat16* src =
                    gsrc[op] + (size_t)row * D_ + c * 32 + ldc16 * 8;
                CP16(dst, src);
            }
        }
        CP_COMMIT();
    };

    load_stage(0);
    load_stage(1);

    float acc[2][8][4];
#pragma unroll
    for (int mt = 0; mt < 2; mt++)
#pragma unroll
        for (int nt = 0; nt < 8; nt++)
#pragma unroll
            for (int r = 0; r < 4; r++) acc[mt][nt][r] = 0.0f;

    for (int c = 0; c < NCHUNK; c++) {
        if (c < NCHUNK - 1) CP_WAIT1(); else CP_WAIT0();
        __syncthreads();
        uint32_t base = sb + (c & 1) * STAGE_B;

#pragma unroll
        for (int s = 0; s < 2; s++) {
            int co = s * 32;
            uint32_t ah[2][4], al[2][4];
#pragma unroll
            for (int mt = 0; mt < 2; mt++) {
                uint32_t addr = base +
                    (warp_m * 32 + mt * 16 + (lane & 15)) * STRIDE +
                    ((lane >> 4) << 4) + co;
                LDSM_X4(ah[mt], addr);
                LDSM_X4(al[mt], addr + TILE_B);
            }
            uint32_t bh[4][4], bl[4][4];
#pragma unroll
            for (int p = 0; p < 4; p++) {
                uint32_t addr = base + 2 * TILE_B +
                    (warp_n * 64 + p * 16 + ((lane >> 4) << 3) + (lane & 7)) * STRIDE +
                    (((lane >> 3) & 1) << 4) + co;
                LDSM_X4(bh[p], addr);
                LDSM_X4(bl[p], addr + TILE_B);
            }
#pragma unroll
            for (int mt = 0; mt < 2; mt++)
#pragma unroll
                for (int nt = 0; nt < 8; nt++) {
                    int p = nt >> 1, hf = (nt & 1) * 2;
                    MMA_BF16(acc[mt][nt], ah[mt], bh[p][hf], bh[p][hf + 1]);
                    MMA_BF16(acc[mt][nt], ah[mt], bl[p][hf], bl[p][hf + 1]);
                    MMA_BF16(acc[mt][nt], al[mt], bh[p][hf], bh[p][hf + 1]);
                }
        }
        __syncthreads();
        if (c + 2 < NCHUNK) load_stage(c + 2);
    }

    // ---- epilogue ----
#pragma unroll
    for (int mt = 0; mt < 2; mt++)
#pragma unroll
        for (int nt = 0; nt < 8; nt++) {
#pragma unroll
            for (int half = 0; half < 2; half++) {
                int m = m0 + warp_m * 32 + mt * 16 + (lane >> 2) + half * 8;
                int n = n0 + warp_n * 64 + nt * 8 + (lane & 3) * 2;
                float2 v = make_float2(acc[mt][nt][half * 2],
                                       acc[mt][nt][half * 2 + 1]);
                if (HEADED) {
                    int b = m >> 11, ss = m & (S_ - 1), h = n >> 6, d = n & 63;
                    *(float2*)&C[((((size_t)b * H_ + h) * S_ + ss) << 6) + d] = v;
                } else {
                    *(float2*)&C[(size_t)m * D_ + n] = v;
                }
            }
        }
}

// ---------------------------------------------------------------------------
// sin/cos table (exact range reduction) + RoPE — unchanged (verified R1)
// ---------------------------------------------------------------------------
__global__ void sincos_table_kernel(const int* __restrict__ pos) {
    int idx = blockIdx.x * blockDim.x + threadIdx.x;
    if (idx >= S_ * 32) return;
    int s = idx >> 5;
    int p = idx & 31;
    float invf = (float)exp2(-(double)p * 0.4152410118609203);
    float ang = (float)pos[s] * invf;
    double a = (double)ang;
    double kq = floor(a * 0.15915494309189535);
    float r = (float)(a - kq * 6.283185307179586);
    float sn, cs;
    sincosf(r, &sn, &cs);
    g_sc[idx] = make_float2(sn, cs);
}

__global__ void rope_kernel(float* __restrict__ X) {
    int idx = blockIdx.x * blockDim.x + threadIdx.x;
    int p = idx & 31;
    int rowId = idx >> 5;
    int s = rowId & (S_ - 1);
    float2 sc = g_sc[(s << 5) | p];
    float2 v = ((float2*)X)[idx];
    ((float2*)X)[idx] = make_float2(v.x * sc.y - v.y * sc.x,
                                    v.x * sc.x + v.y * sc.y);
}

// ---------------------------------------------------------------------------
// Causal flash attention, fp32, ILP-restructured:
// 8-j score blocks, 4-way-split dots, one max/rescale per block, batched exp.
// One thread = one q row. BM=128 (128 thr), K/V streamed in 64-row smem tiles.
// ---------------------------------------------------------------------------
__global__ void __launch_bounds__(128) attn_kernel(const float* __restrict__ Q,
                                                   const float* __restrict__ K,
                                                   const float* __restrict__ V,
                                                   float* __restrict__ O) {
    __shared__ float Ks[64 * DK_];
    __shared__ float Vs[64 * DK_];

    int bh = blockIdx.y;
    int b = bh >> 4;
    int h = bh & 15;
    int row = blockIdx.x * 128 + threadIdx.x;

    const float* qp = Q + ((size_t)bh * S_ + row) * DK_;
    float4 q4[16];
#pragma unroll
    for (int i = 0; i < 16; i++) q4[i] = ((const float4*)qp)[i];

    float o[DK_];
#pragma unroll
    for (int i = 0; i < DK_; i++) o[i] = 0.0f;

    float m = -INFINITY;
    float l = 0.0f;
    const float sc = 0.125f * 1.4426950408889634f;  // 1/sqrt(64) * log2(e)

    int kend = (blockIdx.x + 1) * 128;
    for (int kb = 0; kb < kend; kb += 64) {
        const float4* kp = (const float4*)(K + ((size_t)bh * S_ + kb) * DK_);
        const float4* vp = (const float4*)(V + ((size_t)bh * S_ + kb) * DK_);
#pragma unroll
        for (int i = 0; i < 8; i++) {
            int f = threadIdx.x + i * 128;
            ((float4*)Ks)[f] = kp[f];
            ((float4*)Vs)[f] = vp[f];
        }
        __syncthreads();

#pragma unroll 1
        for (int jb = 0; jb < 64; jb += 8) {
            if (kb + jb > row) break;  // fully-masked blocks (and beyond)
            float s[8];
#pragma unroll
            for (int jj = 0; jj < 8; jj++) {
                const float4* kr = (const float4*)&Ks[(jb + jj) * DK_];
                float s0 = 0.f, s1 = 0.f, s2 = 0.f, s3 = 0.f;
#pragma unroll
                for (int d4 = 0; d4 < 16; d4++) {
                    float4 kk = kr[d4];
                    s0 += q4[d4].x * kk.x;
                    s1 += q4[d4].y * kk.y;
                    s2 += q4[d4].z * kk.z;
                    s3 += q4[d4].w * kk.w;
                }
                float t = (s0 + s1) + (s2 + s3);
                s[jj] = (kb + jb + jj <= row) ? t * sc : -INFINITY;
            }
            float mb = s[0];
#pragma unroll
            for (int jj = 1; jj < 8; jj++) mb = fmaxf(mb, s[jj]);
            if (mb > m) {
                float al2 = exp2f(m - mb);  // exp2f(-inf)=0 on first block
                m = mb;
                l *= al2;
#pragma unroll
                for (int d = 0; d < DK_; d++) o[d] *= al2;
            }
            float p[8];
            float psum = 0.0f;
#pragma unroll
            for (int jj = 0; jj < 8; jj++) {
                p[jj] = exp2f(s[jj] - m);
                psum += p[jj];
            }
            l += psum;
#pragma unroll
            for (int jj = 0; jj < 8; jj++) {
                const float4* vr = (const float4*)&Vs[(jb + jj) * DK_];
#pragma unroll
                for (int d4 = 0; d4 < 16; d4++) {
                    float4 vv = vr[d4];
                    o[4 * d4 + 0] += p[jj] * vv.x;
                    o[4 * d4 + 1] += p[jj] * vv.y;
                    o[4 * d4 + 2] += p[jj] * vv.z;
                    o[4 * d4 + 3] += p[jj] * vv.w;
                }
            }
        }
        __syncthreads();
    }

    float inv = 1.0f / l;
    float* op = O + (((size_t)b * S_ + row) * H_ + h) * DK_;
#pragma unroll
    for (int d4 = 0; d4 < 16; d4++) {
        float4 vv = make_float4(o[4 * d4 + 0] * inv, o[4 * d4 + 1] * inv,
                                o[4 * d4 + 2] * inv, o[4 * d4 + 3] * inv);
        ((float4*)op)[d4] = vv;
    }
}

// ---------------------------------------------------------------------------
// Launch
// ---------------------------------------------------------------------------
extern "C" void kernel_launch(void* const* d_in, const int* in_sizes, int n_in,
                              void* d_out, int out_size) {
    const float* x = (const float*)d_in[0];
    const float* W[4] = {(const float*)d_in[1], (const float*)d_in[2],
                         (const float*)d_in[3], (const float*)d_in[4]};
    const int* pos = (const int*)d_in[5];

    float *q, *k, *v, *attn;
    __nv_bfloat16 *xh, *xl, *ah, *al, *wh, *wl;
    cudaGetSymbolAddress((void**)&q, g_q);
    cudaGetSymbolAddress((void**)&k, g_k);
    cudaGetSymbolAddress((void**)&v, g_v);
    cudaGetSymbolAddress((void**)&attn, g_attn);
    cudaGetSymbolAddress((void**)&xh, g_xh);
    cudaGetSymbolAddress((void**)&xl, g_xl);
    cudaGetSymbolAddress((void**)&ah, g_ah);
    cudaGetSymbolAddress((void**)&al, g_al);
    cudaGetSymbolAddress((void**)&wh, g_wh);
    cudaGetSymbolAddress((void**)&wl, g_wl);

    cudaFuncSetAttribute(gemm_mma<true>,
                         cudaFuncAttributeMaxDynamicSharedMemorySize, GSMEM);
    cudaFuncSetAttribute(gemm_mma<false>,
                         cudaFuncAttributeMaxDynamicSharedMemorySize, GSMEM);

    sincos_table_kernel<<<(S_ * 32) / 256, 256>>>(pos);

    const int NX = B_ * S_ * D_;  // 4M
    const int NW = D_ * D_;       // 1M
    split_kernel<<<NX / 256, 256>>>(x, xh, xl, NX);
    for (int i = 0; i < 4; i++)
        split_kernel<<<NW / 256, 256>>>(W[i], wh + (size_t)i * NW,
                                        wl + (size_t)i * NW, NW);

    dim3 gg(D_ / 128, (B_ * S_) / 128);  // (8, 32)
    gemm_mma<true><<<gg, 256, GSMEM>>>(xh, xl, wh + 0 * (size_t)NW,
                                       wl + 0 * (size_t)NW, q);
    gemm_mma<true><<<gg, 256, GSMEM>>>(xh, xl, wh + 1 * (size_t)NW,
                                       wl + 1 * (size_t)NW, k);
    gemm_mma<true><<<gg, 256, GSMEM>>>(xh, xl, wh + 2 * (size_t)NW,
                                       wl + 2 * (size_t)NW, v);

    int ropeBlocks = (B_ * H_ * S_ * 32) / 256;
    rope_kernel<<<ropeBlocks, 256>>>(q);
    rope_kernel<<<ropeBlocks, 256>>>(k);

    attn_kernel<<<dim3(S_ / 128, B_ * H_), 128>>>(q, k, v, attn);

    split_kernel<<<NX / 256, 256>>>(attn, ah, al, NX);
    gemm_mma<false><<<gg, 256, GSMEM>>>(ah, al, wh + 3 * (size_t)NW,
                                        wl + 3 * (size_t)NW, (float*)d_out);
}

// round 6
// speedup vs baseline: 2.6503x; 1.8094x over previous
#include <cuda_runtime.h>
#include <cuda_bf16.h>
#include <math.h>
#include <cstdint>

// Problem constants
#define B_ 2
#define S_ 2048
#define D_ 1024
#define H_ 16
#define DK_ 64

// ---------------------------------------------------------------------------
// Scratch (__device__ globals; no allocation allowed)
// ---------------------------------------------------------------------------
__device__ float g_q[B_ * S_ * D_];     // [B,H,S,64] f32
__device__ float g_k[B_ * S_ * D_];     // [B,H,S,64] f32
__device__ float g_v[B_ * S_ * D_];     // [B,H,S,64] f32
__device__ float g_attn[B_ * S_ * D_];  // [B,S,H,64] f32
__device__ float2 g_sc[S_ * 32];

// bf16 split buffers (GEMM inputs)
__device__ __nv_bfloat16 g_xh[B_ * S_ * D_];
__device__ __nv_bfloat16 g_xl[B_ * S_ * D_];
__device__ __nv_bfloat16 g_ah[B_ * S_ * D_];
__device__ __nv_bfloat16 g_al[B_ * S_ * D_];
__device__ __nv_bfloat16 g_wh[4][D_ * D_];
__device__ __nv_bfloat16 g_wl[4][D_ * D_];

// bf16 split buffers (attention inputs)
__device__ __nv_bfloat16 g_qh[B_ * S_ * D_];   // [B,H,S,64], pre-scaled
__device__ __nv_bfloat16 g_ql[B_ * S_ * D_];
__device__ __nv_bfloat16 g_kh[B_ * S_ * D_];   // [B,H,S,64]
__device__ __nv_bfloat16 g_kl[B_ * S_ * D_];
__device__ __nv_bfloat16 g_vth[B_ * S_ * D_];  // [B,H,64,S] (transposed)
__device__ __nv_bfloat16 g_vtl[B_ * S_ * D_];

// ---------------------------------------------------------------------------
// PTX helpers (baseline ISA: mma.sync / ldmatrix / cp.async — sm_103-safe)
// ---------------------------------------------------------------------------
__device__ __forceinline__ uint32_t smem_u32(const void* p) {
    uint32_t a;
    asm("{ .reg .u64 t; cvta.to.shared.u64 t, %1; cvt.u32.u64 %0, t; }"
        : "=r"(a) : "l"(p));
    return a;
}

#define CP16(dst, src) \
    asm volatile("cp.async.cg.shared.global [%0], [%1], 16;" \
                 :: "r"(dst), "l"(src))
#define CP_COMMIT() asm volatile("cp.async.commit_group;")
#define CP_WAIT1() asm volatile("cp.async.wait_group 1;")
#define CP_WAIT0() asm volatile("cp.async.wait_group 0;")

#define LDSM_X4(r, a)                                                       \
    asm volatile("ldmatrix.sync.aligned.m8n8.x4.shared.b16 "                \
                 "{%0,%1,%2,%3}, [%4];"                                     \
                 : "=r"((r)[0]), "=r"((r)[1]), "=r"((r)[2]), "=r"((r)[3])   \
                 : "r"(a))

#define MMA_BF16(d, a, b0, b1)                                              \
    asm volatile("mma.sync.aligned.m16n8k16.row.col.f32.bf16.bf16.f32 "     \
                 "{%0,%1,%2,%3},{%4,%5,%6,%7},{%8,%9},{%0,%1,%2,%3};"       \
                 : "+f"((d)[0]), "+f"((d)[1]), "+f"((d)[2]), "+f"((d)[3])   \
                 : "r"((a)[0]), "r"((a)[1]), "r"((a)[2]), "r"((a)[3]),      \
                   "r"(b0), "r"(b1))

// FFMA-only exp2 for t <= 0 (deg-6 Taylor on [-0.5,0.5], rel err ~1.2e-7)
__device__ __forceinline__ float exp2p(float t) {
    t = fmaxf(t, -80.0f);
    float y = __fadd_rn(t, 12582912.0f);              // round-to-nearest int
    int n = __float_as_int(y) - 0x4B400000;
    float f = __fsub_rn(t, __fsub_rn(y, 12582912.0f));
    float p = 1.54035304e-4f;
    p = fmaf(p, f, 1.33335581e-3f);
    p = fmaf(p, f, 9.61812911e-3f);
    p = fmaf(p, f, 5.55041087e-2f);
    p = fmaf(p, f, 2.40226507e-1f);
    p = fmaf(p, f, 6.93147181e-1f);
    p = fmaf(p, f, 1.0f);
    return __int_as_float(__float_as_int(p) + (n << 23));
}

__device__ __forceinline__ uint32_t pack_bf2(float lo, float hi) {
    __nv_bfloat162 h = __floats2bfloat162_rn(lo, hi);
    return *(uint32_t*)&h;
}

// ---------------------------------------------------------------------------
// fp32 -> (hi, lo) bf16 split (GEMM inputs)
// ---------------------------------------------------------------------------
__global__ void split_kernel(const float* __restrict__ in,
                             __nv_bfloat16* __restrict__ hi,
                             __nv_bfloat16* __restrict__ lo, int n) {
    int i = blockIdx.x * blockDim.x + threadIdx.x;
    if (i >= n) return;
    float v = in[i];
    __nv_bfloat16 h = __float2bfloat16(v);
    hi[i] = h;
    lo[i] = __float2bfloat16(v - __bfloat162float(h));
}

// ---------------------------------------------------------------------------
// HMMA bf16-split GEMM (verified R4): C[M,1024] = A[M,1024] @ W[N,1024]^T
// ---------------------------------------------------------------------------
#define NCHUNK 32
#define STRIDE 80
#define TILE_B (128 * STRIDE)
#define STAGE_B (4 * TILE_B)
#define GSMEM (2 * STAGE_B)

template <bool HEADED>
__global__ void __launch_bounds__(256, 1) gemm_mma(
    const __nv_bfloat16* __restrict__ Ah, const __nv_bfloat16* __restrict__ Al,
    const __nv_bfloat16* __restrict__ Bh, const __nv_bfloat16* __restrict__ Bl,
    float* __restrict__ C) {
    extern __shared__ char sm[];
    uint32_t sb = smem_u32(sm);
    int tid = threadIdx.x;
    int lane = tid & 31;
    int wid = tid >> 5;
    int warp_m = wid & 3;
    int warp_n = wid >> 2;
    int m0 = blockIdx.y * 128;
    int n0 = blockIdx.x * 128;

    const __nv_bfloat16* gsrc[4] = {
        Ah + (size_t)m0 * D_, Al + (size_t)m0 * D_,
        Bh + (size_t)n0 * D_, Bl + (size_t)n0 * D_};

    int ldrow = tid >> 2;
    int ldc16 = tid & 3;

    auto load_stage = [&](int c) {
        uint32_t dbase = sb + (c & 1) * STAGE_B;
#pragma unroll
        for (int op = 0; op < 4; op++) {
#pragma unroll
            for (int i = 0; i < 2; i++) {
                int row = ldrow + i * 64;
                uint32_t dst = dbase + op * TILE_B + row * STRIDE + ldc16 * 16;
                const __nv_bfloat16* src =
                    gsrc[op] + (size_t)row * D_ + c * 32 + ldc16 * 8;
                CP16(dst, src);
            }
        }
        CP_COMMIT();
    };

    load_stage(0);
    load_stage(1);

    float acc[2][8][4];
#pragma unroll
    for (int mt = 0; mt < 2; mt++)
#pragma unroll
        for (int nt = 0; nt < 8; nt++)
#pragma unroll
            for (int r = 0; r < 4; r++) acc[mt][nt][r] = 0.0f;

    for (int c = 0; c < NCHUNK; c++) {
        if (c < NCHUNK - 1) CP_WAIT1(); else CP_WAIT0();
        __syncthreads();
        uint32_t base = sb + (c & 1) * STAGE_B;

#pragma unroll
        for (int s = 0; s < 2; s++) {
            int co = s * 32;
            uint32_t ah[2][4], al[2][4];
#pragma unroll
            for (int mt = 0; mt < 2; mt++) {
                uint32_t addr = base +
                    (warp_m * 32 + mt * 16 + (lane & 15)) * STRIDE +
                    ((lane >> 4) << 4) + co;
                LDSM_X4(ah[mt], addr);
                LDSM_X4(al[mt], addr + TILE_B);
            }
            uint32_t bh[4][4], bl[4][4];
#pragma unroll
            for (int p = 0; p < 4; p++) {
                uint32_t addr = base + 2 * TILE_B +
                    (warp_n * 64 + p * 16 + ((lane >> 4) << 3) + (lane & 7)) * STRIDE +
                    (((lane >> 3) & 1) << 4) + co;
                LDSM_X4(bh[p], addr);
                LDSM_X4(bl[p], addr + TILE_B);
            }
#pragma unroll
            for (int mt = 0; mt < 2; mt++)
#pragma unroll
                for (int nt = 0; nt < 8; nt++) {
                    int p = nt >> 1, hf = (nt & 1) * 2;
                    MMA_BF16(acc[mt][nt], ah[mt], bh[p][hf], bh[p][hf + 1]);
                    MMA_BF16(acc[mt][nt], ah[mt], bl[p][hf], bl[p][hf + 1]);
                    MMA_BF16(acc[mt][nt], al[mt], bh[p][hf], bh[p][hf + 1]);
                }
        }
        __syncthreads();
        if (c + 2 < NCHUNK) load_stage(c + 2);
    }

#pragma unroll
    for (int mt = 0; mt < 2; mt++)
#pragma unroll
        for (int nt = 0; nt < 8; nt++) {
#pragma unroll
            for (int half = 0; half < 2; half++) {
                int m = m0 + warp_m * 32 + mt * 16 + (lane >> 2) + half * 8;
                int n = n0 + warp_n * 64 + nt * 8 + (lane & 3) * 2;
                float2 v = make_float2(acc[mt][nt][half * 2],
                                       acc[mt][nt][half * 2 + 1]);
                if (HEADED) {
                    int b = m >> 11, ss = m & (S_ - 1), h = n >> 6, d = n & 63;
                    *(float2*)&C[((((size_t)b * H_ + h) * S_ + ss) << 6) + d] = v;
                } else {
                    *(float2*)&C[(size_t)m * D_ + n] = v;
                }
            }
        }
}

// ---------------------------------------------------------------------------
// sin/cos table (exact range reduction)
// ---------------------------------------------------------------------------
__global__ void sincos_table_kernel(const int* __restrict__ pos) {
    int idx = blockIdx.x * blockDim.x + threadIdx.x;
    if (idx >= S_ * 32) return;
    int s = idx >> 5;
    int p = idx & 31;
    float invf = (float)exp2(-(double)p * 0.4152410118609203);
    float ang = (float)pos[s] * invf;
    double a = (double)ang;
    double kq = floor(a * 0.15915494309189535);
    float r = (float)(a - kq * 6.283185307179586);
    float sn, cs;
    sincosf(r, &sn, &cs);
    g_sc[idx] = make_float2(sn, cs);
}

// ---------------------------------------------------------------------------
// RoPE + bf16 hi/lo split (q additionally scaled by 1/8*log2(e))
// ---------------------------------------------------------------------------
__global__ void rope_split_kernel(const float* __restrict__ X,
                                  __nv_bfloat16* __restrict__ Xh,
                                  __nv_bfloat16* __restrict__ Xl, float scale) {
    int idx = blockIdx.x * blockDim.x + threadIdx.x;  // B*H*S*32 pairs
    int p = idx & 31;
    int s = (idx >> 5) & (S_ - 1);
    float2 sc = g_sc[(s << 5) | p];
    float2 v = ((const float2*)X)[idx];
    float y0 = (v.x * sc.y - v.y * sc.x) * scale;
    float y1 = (v.x * sc.x + v.y * sc.y) * scale;
    __nv_bfloat16 h0 = __float2bfloat16(y0);
    __nv_bfloat16 h1 = __float2bfloat16(y1);
    __nv_bfloat162 hh; hh.x = h0; hh.y = h1;
    ((__nv_bfloat162*)Xh)[idx] = hh;
    __nv_bfloat162 ll;
    ll.x = __float2bfloat16(y0 - __bfloat162float(h0));
    ll.y = __float2bfloat16(y1 - __bfloat162float(h1));
    ((__nv_bfloat162*)Xl)[idx] = ll;
}

// ---------------------------------------------------------------------------
// V: split + transpose to [B,H,64,S] via smem tiles
// ---------------------------------------------------------------------------
__global__ void __launch_bounds__(256) vsplit_t_kernel(
    const float* __restrict__ V, __nv_bfloat16* __restrict__ Vth,
    __nv_bfloat16* __restrict__ Vtl) {
    __shared__ float t[64][65];
    int bh = blockIdx.y;
    int s0 = blockIdx.x * 64;
    int tid = threadIdx.x;
#pragma unroll
    for (int i = 0; i < 16; i++) {
        int e = tid + i * 256;
        int s = e >> 6, d = e & 63;
        t[d][s] = V[((size_t)bh * S_ + s0 + s) * 64 + d];
    }
    __syncthreads();
#pragma unroll
    for (int i = 0; i < 16; i++) {
        int e = tid + i * 256;
        int d = e >> 6, sj = e & 63;
        float val = t[d][sj];
        __nv_bfloat16 h = __float2bfloat16(val);
        size_t o = ((size_t)bh * 64 + d) * S_ + s0 + sj;
        Vth[o] = h;
        Vtl[o] = __float2bfloat16(val - __bfloat162float(h));
    }
}

// ---------------------------------------------------------------------------
// Tensor-core causal flash attention (bf16 split, fp32 accum, poly exp2).
// CTA: 128 q rows, 4 warps x 32 rows. j blocks of 64. Q/K/V all in smem,
// non-trans ldmatrix everywhere (V pre-transposed). Output [B,S,H,64] f32.
// ---------------------------------------------------------------------------
#define AST 144                       // smem row stride (bytes)
#define AQ_B (128 * AST)              // 18432 per Q tile (h or l)
#define AKV_TILE (64 * AST)           // 9216 per 64x64 bf16 tile
#define AKV_STAGE (4 * AKV_TILE)      // 36864: KH,KL,VH,VL
#define A_OST (2 * AQ_B)              // stages start after Qh,Ql
#define ASMEM (A_OST + 2 * AKV_STAGE) // 110592

__global__ void __launch_bounds__(128, 2) attn_mma(
    const __nv_bfloat16* __restrict__ Qh, const __nv_bfloat16* __restrict__ Ql,
    const __nv_bfloat16* __restrict__ Kh, const __nv_bfloat16* __restrict__ Kl,
    const __nv_bfloat16* __restrict__ Vth, const __nv_bfloat16* __restrict__ Vtl,
    float* __restrict__ O) {
    extern __shared__ char sm[];
    uint32_t sb = smem_u32(sm);
    int tid = threadIdx.x;
    int lane = tid & 31;
    int wm = tid >> 5;
    int bh = blockIdx.y;
    int q0 = blockIdx.x * 128;
    size_t bhS = (size_t)bh * S_;
    int g = lane >> 2, t4 = lane & 3;

    // ---- load Q (both splits), one commit group ----
    {
        const __nv_bfloat16* sh = Qh + (bhS + q0 + tid) * 64;
        const __nv_bfloat16* sl = Ql + (bhS + q0 + tid) * 64;
        uint32_t dh = sb + tid * AST;
        uint32_t dl = sb + AQ_B + tid * AST;
#pragma unroll
        for (int c = 0; c < 8; c++) {
            CP16(dh + c * 16, sh + c * 8);
            CP16(dl + c * 16, sl + c * 8);
        }
        CP_COMMIT();
    }

    int nblocks = blockIdx.x * 2 + 2;

    int krow = tid >> 1;           // 0..63
    int hc = (tid & 1) * 4;        // chunk base 0 or 4
    auto load_kv = [&](int c) {
        uint32_t base = sb + A_OST + (c & 1) * AKV_STAGE;
        int kb = c * 64;
        const __nv_bfloat16* skh = Kh + (bhS + kb + krow) * 64 + hc * 8;
        const __nv_bfloat16* skl = Kl + (bhS + kb + krow) * 64 + hc * 8;
        const __nv_bfloat16* svh = Vth + ((size_t)bh * 64 + krow) * S_ + kb + hc * 8;
        const __nv_bfloat16* svl = Vtl + ((size_t)bh * 64 + krow) * S_ + kb + hc * 8;
        uint32_t d0 = base + krow * AST + hc * 16;
#pragma unroll
        for (int i = 0; i < 4; i++) {
            CP16(d0 + i * 16, skh + i * 8);
            CP16(d0 + AKV_TILE + i * 16, skl + i * 8);
            CP16(d0 + 2 * AKV_TILE + i * 16, svh + i * 8);
            CP16(d0 + 3 * AKV_TILE + i * 16, svl + i * 8);
        }
        CP_COMMIT();
    };
    load_kv(0);
    load_kv(1);

    float o[2][8][4];
    float Sv[2][8][4];
    float mr[2][2], lr[2][2];
#pragma unroll
    for (int mt = 0; mt < 2; mt++) {
#pragma unroll
        for (int nt = 0; nt < 8; nt++)
#pragma unroll
            for (int r = 0; r < 4; r++) o[mt][nt][r] = 0.0f;
        mr[mt][0] = mr[mt][1] = -INFINITY;
        lr[mt][0] = lr[mt][1] = 0.0f;
    }

    for (int c = 0; c < nblocks; c++) {
        if (c == nblocks - 1) CP_WAIT0(); else CP_WAIT1();
        __syncthreads();
        uint32_t base = sb + A_OST + (c & 1) * AKV_STAGE;
        int kb = c * 64;

#pragma unroll
        for (int mt = 0; mt < 2; mt++)
#pragma unroll
            for (int nt = 0; nt < 8; nt++)
#pragma unroll
                for (int r = 0; r < 4; r++) Sv[mt][nt][r] = 0.0f;

        // ---- S = Q K^T (3 split passes) ----
#pragma unroll
        for (int ks = 0; ks < 4; ks++) {
            uint32_t ah[2][4], al[2][4];
#pragma unroll
            for (int mt = 0; mt < 2; mt++) {
                uint32_t qa = sb + (wm * 32 + mt * 16 + (lane & 15)) * AST +
                              ks * 32 + ((lane >> 4) << 4);
                LDSM_X4(ah[mt], qa);
                LDSM_X4(al[mt], qa + AQ_B);
            }
#pragma unroll
            for (int ntp = 0; ntp < 4; ntp++) {
                uint32_t ba = base +
                    (ntp * 16 + ((lane >> 4) << 3) + (lane & 7)) * AST +
                    ks * 32 + (((lane >> 3) & 1) << 4);
                uint32_t bhf[4], blf[4];
                LDSM_X4(bhf, ba);
                LDSM_X4(blf, ba + AKV_TILE);
#pragma unroll
                for (int mt = 0; mt < 2; mt++)
#pragma unroll
                    for (int sub = 0; sub < 2; sub++) {
                        int nt = ntp * 2 + sub;
                        MMA_BF16(Sv[mt][nt], ah[mt], bhf[sub * 2], bhf[sub * 2 + 1]);
                        MMA_BF16(Sv[mt][nt], ah[mt], blf[sub * 2], blf[sub * 2 + 1]);
                        MMA_BF16(Sv[mt][nt], al[mt], bhf[sub * 2], bhf[sub * 2 + 1]);
                    }
            }
        }

        // ---- causal mask (only near diagonal) ----
        if (kb + 63 > q0 + wm * 32) {
#pragma unroll
            for (int mt = 0; mt < 2; mt++)
#pragma unroll
                for (int nt = 0; nt < 8; nt++)
#pragma unroll
                    for (int r = 0; r < 4; r++) {
                        int col = kb + nt * 8 + t4 * 2 + (r & 1);
                        int row = q0 + wm * 32 + mt * 16 + g + (r >> 1) * 8;
                        if (col > row) Sv[mt][nt][r] = -INFINITY;
                    }
        }

        // ---- online softmax (FFMA poly exp2) ----
#pragma unroll
        for (int mt = 0; mt < 2; mt++)
#pragma unroll
            for (int h = 0; h < 2; h++) {
                float mx = Sv[mt][0][2 * h];
#pragma unroll
                for (int nt = 0; nt < 8; nt++) {
                    mx = fmaxf(mx, Sv[mt][nt][2 * h]);
                    mx = fmaxf(mx, Sv[mt][nt][2 * h + 1]);
                }
                mx = fmaxf(mx, __shfl_xor_sync(0xffffffff, mx, 1));
                mx = fmaxf(mx, __shfl_xor_sync(0xffffffff, mx, 2));
                float mn = fmaxf(mr[mt][h], mx);
                float alpha = exp2p(mr[mt][h] - mn);
                mr[mt][h] = mn;
                float ps = 0.0f;
#pragma unroll
                for (int nt = 0; nt < 8; nt++) {
                    o[mt][nt][2 * h] *= alpha;
                    o[mt][nt][2 * h + 1] *= alpha;
                    float p0 = exp2p(Sv[mt][nt][2 * h] - mn);
                    float p1 = exp2p(Sv[mt][nt][2 * h + 1] - mn);
                    Sv[mt][nt][2 * h] = p0;
                    Sv[mt][nt][2 * h + 1] = p1;
                    ps += p0 + p1;
                }
                ps += __shfl_xor_sync(0xffffffff, ps, 1);
                ps += __shfl_xor_sync(0xffffffff, ps, 2);
                lr[mt][h] = lr[mt][h] * alpha + ps;
            }

        // ---- O += P V (3 split passes); P split built from registers ----
#pragma unroll
        for (int ks = 0; ks < 4; ks++) {
            uint32_t ph[2][4], pl[2][4];
#pragma unroll
            for (int mt = 0; mt < 2; mt++)
#pragma unroll
                for (int u = 0; u < 4; u++) {
                    int nt = 2 * ks + (u >> 1);
                    int r0 = (u & 1) * 2;
                    float p0 = Sv[mt][nt][r0], p1 = Sv[mt][nt][r0 + 1];
                    __nv_bfloat162 hh = __floats2bfloat162_rn(p0, p1);
                    ph[mt][u] = *(uint32_t*)&hh;
                    pl[mt][u] = pack_bf2(p0 - __bfloat162float(hh.x),
                                         p1 - __bfloat162float(hh.y));
                }
#pragma unroll
            for (int ntp = 0; ntp < 4; ntp++) {
                uint32_t va = base + 2 * AKV_TILE +
                    (ntp * 16 + ((lane >> 4) << 3) + (lane & 7)) * AST +
                    ks * 32 + (((lane >> 3) & 1) << 4);
                uint32_t bvh[4], bvl[4];
                LDSM_X4(bvh, va);
                LDSM_X4(bvl, va + AKV_TILE);
#pragma unroll
                for (int mt = 0; mt < 2; mt++)
#pragma unroll
                    for (int sub = 0; sub < 2; sub++) {
                        int nt = ntp * 2 + sub;
                        MMA_BF16(o[mt][nt], ph[mt], bvh[sub * 2], bvh[sub * 2 + 1]);
                        MMA_BF16(o[mt][nt], ph[mt], bvl[sub * 2], bvl[sub * 2 + 1]);
                        MMA_BF16(o[mt][nt], pl[mt], bvh[sub * 2], bvh[sub * 2 + 1]);
                    }
            }
        }

        __syncthreads();
        if (c + 2 < nblocks) load_kv(c + 2);
    }

    // ---- epilogue: normalize, write [B,S,H,64] ----
    int b = bh >> 4, hh = bh & 15;
#pragma unroll
    for (int mt = 0; mt < 2; mt++)
#pragma unroll
        for (int h = 0; h < 2; h++) {
            float inv = 1.0f / lr[mt][h];
            int row = q0 + wm * 32 + mt * 16 + g + 8 * h;
#pragma unroll
            for (int nt = 0; nt < 8; nt++) {
                int d = nt * 8 + t4 * 2;
                float2 val = make_float2(o[mt][nt][2 * h] * inv,
                                         o[mt][nt][2 * h + 1] * inv);
                *(float2*)&O[(((size_t)b * S_ + row) * H_ + hh) * 64 + d] = val;
            }
        }
}

// ---------------------------------------------------------------------------
// Launch
// ---------------------------------------------------------------------------
extern "C" void kernel_launch(void* const* d_in, const int* in_sizes, int n_in,
                              void* d_out, int out_size) {
    const float* x = (const float*)d_in[0];
    const float* W[4] = {(const float*)d_in[1], (const float*)d_in[2],
                         (const float*)d_in[3], (const float*)d_in[4]};
    const int* pos = (const int*)d_in[5];

    float *q, *k, *v, *attn;
    __nv_bfloat16 *xh, *xl, *ah, *al, *wh, *wl;
    __nv_bfloat16 *qh, *ql, *kh, *kl, *vth, *vtl;
    cudaGetSymbolAddress((void**)&q, g_q);
    cudaGetSymbolAddress((void**)&k, g_k);
    cudaGetSymbolAddress((void**)&v, g_v);
    cudaGetSymbolAddress((void**)&attn, g_attn);
    cudaGetSymbolAddress((void**)&xh, g_xh);
    cudaGetSymbolAddress((void**)&xl, g_xl);
    cudaGetSymbolAddress((void**)&ah, g_ah);
    cudaGetSymbolAddress((void**)&al, g_al);
    cudaGetSymbolAddress((void**)&wh, g_wh);
    cudaGetSymbolAddress((void**)&wl, g_wl);
    cudaGetSymbolAddress((void**)&qh, g_qh);
    cudaGetSymbolAddress((void**)&ql, g_ql);
    cudaGetSymbolAddress((void**)&kh, g_kh);
    cudaGetSymbolAddress((void**)&kl, g_kl);
    cudaGetSymbolAddress((void**)&vth, g_vth);
    cudaGetSymbolAddress((void**)&vtl, g_vtl);

    cudaFuncSetAttribute(gemm_mma<true>,
                         cudaFuncAttributeMaxDynamicSharedMemorySize, GSMEM);
    cudaFuncSetAttribute(gemm_mma<false>,
                         cudaFuncAttributeMaxDynamicSharedMemorySize, GSMEM);
    cudaFuncSetAttribute(attn_mma,
                         cudaFuncAttributeMaxDynamicSharedMemorySize, ASMEM);

    sincos_table_kernel<<<(S_ * 32) / 256, 256>>>(pos);

    const int NX = B_ * S_ * D_;
    const int NW = D_ * D_;
    split_kernel<<<NX / 256, 256>>>(x, xh, xl, NX);
    for (int i = 0; i < 4; i++)
        split_kernel<<<NW / 256, 256>>>(W[i], wh + (size_t)i * NW,
                                        wl + (size_t)i * NW, NW);

    dim3 gg(D_ / 128, (B_ * S_) / 128);
    gemm_mma<true><<<gg, 256, GSMEM>>>(xh, xl, wh + 0 * (size_t)NW,
                                       wl + 0 * (size_t)NW, q);
    gemm_mma<true><<<gg, 256, GSMEM>>>(xh, xl, wh + 1 * (size_t)NW,
                                       wl + 1 * (size_t)NW, k);
    gemm_mma<true><<<gg, 256, GSMEM>>>(xh, xl, wh + 2 * (size_t)NW,
                                       wl + 2 * (size_t)NW, v);

    const float QSCALE = 0.125f * 1.4426950408889634f;  // 1/sqrt(64)*log2(e)
    int rsBlocks = (B_ * H_ * S_ * 32) / 256;
    rope_split_kernel<<<rsBlocks, 256>>>(q, qh, ql, QSCALE);
    rope_split_kernel<<<rsBlocks, 256>>>(k, kh, kl, 1.0f);
    vsplit_t_kernel<<<dim3(S_ / 64, B_ * H_), 256>>>(v, vth, vtl);

    attn_mma<<<dim3(S_ / 128, B_ * H_), 128, ASMEM>>>(qh, ql, kh, kl, vth, vtl,
                                                      attn);

    split_kernel<<<NX / 256, 256>>>(attn, ah, al, NX);
    gemm_mma<false><<<gg, 256, GSMEM>>>(ah, al, wh + 3 * (size_t)NW,
                                        wl + 3 * (size_t)NW, (float*)d_out);
}